// round 17
// baseline (speedup 1.0000x reference)
#include <cuda_runtime.h>
#include <cuda_bf16.h>
#include <stdint.h>

// ---------------------------------------------------------------------------
// HardTripletMiningLoss  (n=3B=480, D=128)
//   gram = E E^T ;  pd[i,j] = max(sq_i + sq_j - 2 gram_ij, 0)
//   loss = mean over {i!=0, lab[i]==lab[j], lab[k]!=lab[j], td>0} of
//          td = pd[i,j] - pd[j,k] + A
// R17: tf32 hi/lo split HOISTED into a one-pass prep kernel (was re-done by
//      every gram block: 2.7M redundant cvt chains, alu=13%). Gram staging is
//      now pure float4 copies. PDL chain prep -> gram -> triplet -> final.
// ---------------------------------------------------------------------------

#define MAX_N    768
#define MAXD     128
#define MAXW     ((MAX_N + 31) / 32)
#define POSCAP   128
#define MARGIN_A 0.2f
#define GTR      16      // gram tile rows
#define GTC      32      // gram tile cols
#define KCH      64      // K chunk
#define SSTR     68      // smem row stride (== 4 mod 32 -> conflict-free frags)
#define TTH      256     // triplet threads
#define TNW      8

static __device__ float g_Ehi[MAX_N * MAXD];
static __device__ float g_Elo[MAX_N * MAXD];
static __device__ float g_gram[MAX_N * MAX_N];
static __device__ float g_sq[MAX_N];
static __device__ float g_ps[MAX_N];
static __device__ int   g_pc[MAX_N];

__device__ __forceinline__ void pdl_wait() {
    asm volatile("griddepcontrol.wait;" ::: "memory");
}
__device__ __forceinline__ void pdl_launch_dependents() {
    asm volatile("griddepcontrol.launch_dependents;" ::: "memory");
}
__device__ __forceinline__ uint32_t tf32_hi(float x) {
    uint32_t h;
    asm("cvt.rna.tf32.f32 %0, %1;" : "=r"(h) : "f"(x));
    return h;
}
__device__ __forceinline__ void tf32_split(float x, uint32_t& hi, uint32_t& lo) {
    hi = tf32_hi(x);
    lo = tf32_hi(x - __uint_as_float(hi));
}
__device__ __forceinline__ void mma_tf32(float c[4],
                                         uint32_t a0, uint32_t a1, uint32_t a2, uint32_t a3,
                                         uint32_t b0, uint32_t b1) {
    asm volatile(
        "mma.sync.aligned.m16n8k8.row.col.f32.tf32.tf32.f32 "
        "{%0,%1,%2,%3},{%4,%5,%6,%7},{%8,%9},{%0,%1,%2,%3};"
        : "+f"(c[0]), "+f"(c[1]), "+f"(c[2]), "+f"(c[3])
        : "r"(a0), "r"(a1), "r"(a2), "r"(a3), "r"(b0), "r"(b1));
}

__device__ __forceinline__ const float* row_ptr(const float* a, const float* p,
                                                const float* ng, int r, int B, int D) {
    if (r < B)      return a  + (size_t)r * D;
    if (r < 2 * B)  return p  + (size_t)(r - B) * D;
    return ng + (size_t)(r - 2 * B) * D;
}

// ---------------------------------------------------------------------------
// prep: one pass over the embedding matrix, split each float to tf32 hi/lo.
// grid: ceil(n*D/4 / 256) blocks of 256.
// ---------------------------------------------------------------------------
__global__ void prep_kernel(const float* __restrict__ anchor,
                            const float* __restrict__ positive,
                            const float* __restrict__ negative,
                            int n, int B, int D) {
    const int i4   = blockIdx.x * blockDim.x + threadIdx.x;
    const int nf4  = D >> 2;
    const int tot4 = n * nf4;
    if (i4 < tot4) {
        const int r  = i4 / nf4;
        const int c4 = i4 - r * nf4;
        const float4 v = ((const float4*)row_ptr(anchor, positive, negative, r, B, D))[c4];
        uint32_t h0, l0, h1, l1, h2, l2, h3, l3;
        tf32_split(v.x, h0, l0); tf32_split(v.y, h1, l1);
        tf32_split(v.z, h2, l2); tf32_split(v.w, h3, l3);
        float4 hv, lv;
        hv.x = __uint_as_float(h0); hv.y = __uint_as_float(h1);
        hv.z = __uint_as_float(h2); hv.w = __uint_as_float(h3);
        lv.x = __uint_as_float(l0); lv.y = __uint_as_float(l1);
        lv.z = __uint_as_float(l2); lv.w = __uint_as_float(l3);
        *(float4*)&g_Ehi[r * MAXD + c4 * 4] = hv;
        *(float4*)&g_Elo[r * MAXD + c4 * 4] = lv;
    }
    pdl_launch_dependents();
}

// ---------------------------------------------------------------------------
// gram (tensor): grid (15, 30), 128 thr. Tile 16 rows x 32 cols. Staging is
// pure float4 copies from pre-split g_Ehi/g_Elo (L2-resident).
// ---------------------------------------------------------------------------
__global__ void __launch_bounds__(128)
gram_kernel(int n, int D) {
    __shared__ float sAh[GTR * SSTR];
    __shared__ float sAl[GTR * SSTR];
    __shared__ float sBh[GTC * SSTR];
    __shared__ float sBl[GTC * SSTR];

    const int bi   = blockIdx.y * GTR;
    const int bj   = blockIdx.x * GTC;
    const int tid  = threadIdx.x;        // 128
    const int lane = tid & 31;
    const int wid  = tid >> 5;           // 0..3 -> col strip
    const int g    = lane >> 2;          // 0..7
    const int tg   = lane & 3;           // 0..3

    pdl_wait();                          // g_Ehi/g_Elo ready

    float acc[4] = {0.f, 0.f, 0.f, 0.f};

    const int nch = (D + KCH - 1) / KCH;
    for (int ch = 0; ch < nch; ch++) {
        const int k0 = ch * KCH;

        // stage A: 16 rows x 16 float4 (hi+lo) -> 2 per thread each
        #pragma unroll
        for (int t = 0; t < 2; t++) {
            const int idx = tid + t * 128;         // 0..255
            const int r   = idx >> 4;              // 0..15
            const int kk  = (idx & 15) * 4;        // 0..60
            const int gr  = (bi + r < n) ? bi + r : n - 1;
            const int go  = gr * MAXD + k0 + kk;
            *(float4*)&sAh[r * SSTR + kk] = *(const float4*)&g_Ehi[go];
            *(float4*)&sAl[r * SSTR + kk] = *(const float4*)&g_Elo[go];
        }
        // stage B: 32 rows x 16 float4 -> 4 per thread each
        #pragma unroll
        for (int t = 0; t < 4; t++) {
            const int idx = tid + t * 128;         // 0..511
            const int r   = idx >> 4;              // 0..31
            const int kk  = (idx & 15) * 4;
            const int gc  = (bj + r < n) ? bj + r : n - 1;
            const int go  = gc * MAXD + k0 + kk;
            *(float4*)&sBh[r * SSTR + kk] = *(const float4*)&g_Ehi[go];
            *(float4*)&sBl[r * SSTR + kk] = *(const float4*)&g_Elo[go];
        }
        __syncthreads();

        // mainloop: 8 k-steps of 8
        #pragma unroll
        for (int s = 0; s < KCH / 8; s++) {
            const int ka = s * 8 + tg;
            const int r0 = g * SSTR;
            const int r1 = r0 + 8 * SSTR;
            const uint32_t ah0 = __float_as_uint(sAh[r0 + ka]);
            const uint32_t ah1 = __float_as_uint(sAh[r1 + ka]);
            const uint32_t ah2 = __float_as_uint(sAh[r0 + ka + 4]);
            const uint32_t ah3 = __float_as_uint(sAh[r1 + ka + 4]);
            const uint32_t al0 = __float_as_uint(sAl[r0 + ka]);
            const uint32_t al1 = __float_as_uint(sAl[r1 + ka]);
            const uint32_t al2 = __float_as_uint(sAl[r0 + ka + 4]);
            const uint32_t al3 = __float_as_uint(sAl[r1 + ka + 4]);
            const int cb = (wid * 8 + g) * SSTR;
            const uint32_t bh0 = __float_as_uint(sBh[cb + ka]);
            const uint32_t bh1 = __float_as_uint(sBh[cb + ka + 4]);
            const uint32_t bl0 = __float_as_uint(sBl[cb + ka]);
            const uint32_t bl1 = __float_as_uint(sBl[cb + ka + 4]);
            mma_tf32(acc, al0, al1, al2, al3, bh0, bh1);
            mma_tf32(acc, ah0, ah1, ah2, ah3, bl0, bl1);
            mma_tf32(acc, ah0, ah1, ah2, ah3, bh0, bh1);
        }
        __syncthreads();
    }

    // epilogue: float2 stores + diagonal extraction
    const int gi0 = bi + g;
    const int gi1 = gi0 + 8;
    const int gj  = bj + wid * 8 + 2 * tg;
    if (gj < n) {
        if (gi0 < n) {
            *(float2*)&g_gram[(size_t)gi0 * n + gj] = make_float2(acc[0], acc[1]);
            if      (gj     == gi0) g_sq[gi0] = acc[0];
            else if (gj + 1 == gi0) g_sq[gi0] = acc[1];
        }
        if (gi1 < n) {
            *(float2*)&g_gram[(size_t)gi1 * n + gj] = make_float2(acc[2], acc[3]);
            if      (gj     == gi1) g_sq[gi1] = acc[2];
            else if (gj + 1 == gi1) g_sq[gi1] = acc[3];
        }
    }
    pdl_launch_dependents();
}

// ---------------------------------------------------------------------------
// Triplet: one block (256 thr) per j. Label work BEFORE pdl_wait (overlaps
// gram); single-matrix reconstruct after. Branch-free fp32 hot loop.
// ---------------------------------------------------------------------------
__global__ void triplet_kernel(const int* __restrict__ ind, int n) {
    __shared__ float    pdrow[MAX_N];
    __shared__ int      labs[MAX_N];
    __shared__ short    slist[POSCAP];
    __shared__ float    avals[POSCAP];
    __shared__ unsigned chunkMask[MAXW];
    __shared__ int      chunkOff[MAXW];
    __shared__ int      nSame;
    __shared__ float    red_s[TNW];
    __shared__ int      red_c[TNW];

    const int j    = blockIdx.x;
    const int tid  = threadIdx.x;
    const int lane = tid & 31;
    const int wid  = tid >> 5;

    // ---------------- pre-wait: everything independent of gram --------------
    for (int t = tid; t < n; t += TTH)
        labs[t] = ind[t];
    __syncthreads();

    const int labj = labs[j];

    const int nChunks = (n + 31) >> 5;
    for (int c = wid; c < nChunks; c += TNW) {
        const int t = (c << 5) + lane;
        const bool pred = (t < n) && (t != 0) && (labs[t] == labj);
        const unsigned m = __ballot_sync(0xffffffffu, pred);
        if (lane == 0) chunkMask[c] = m;
    }
    __syncthreads();
    if (wid == 0) {                       // warp scan (nChunks <= 32)
        const unsigned m = (lane < nChunks) ? chunkMask[lane] : 0u;
        int p = __popc(m);
        #pragma unroll
        for (int o = 1; o < 32; o <<= 1) {
            const int t = __shfl_up_sync(0xffffffffu, p, o);
            if (lane >= o) p += t;
        }
        if (lane < nChunks) chunkOff[lane] = p - __popc(m);
        if (lane == 31) nSame = p;
    }
    __syncthreads();
    for (int c = wid; c < nChunks; c += TNW) {
        const unsigned m = chunkMask[c];
        const int t = (c << 5) + lane;
        if ((m >> lane) & 1u) {
            const int off = chunkOff[c] + __popc(m & ((1u << lane) - 1u));
            if (off < POSCAP) slist[off] = (short)t;
        }
    }
    __syncthreads();

    // ---------------- wait for gram, then consume its output ----------------
    pdl_wait();

    const float sqj = g_sq[j];
    const float* rowp = g_gram + (size_t)j * n;
    const int n4 = n >> 2;
    for (int v = tid; v < n4; v += TTH) {
        const float4 gv = ((const float4*)rowp)[v];
        const float4 qv = ((const float4*)g_sq)[v];
        float4 pd;
        pd.x = fmaxf(fmaf(-2.f, gv.x, sqj + qv.x), 0.f);
        pd.y = fmaxf(fmaf(-2.f, gv.y, sqj + qv.y), 0.f);
        pd.z = fmaxf(fmaf(-2.f, gv.z, sqj + qv.z), 0.f);
        pd.w = fmaxf(fmaf(-2.f, gv.w, sqj + qv.w), 0.f);
        ((float4*)pdrow)[v] = pd;
    }
    for (int v = (n4 << 2) + tid; v < n; v += TTH)
        pdrow[v] = fmaxf(fmaf(-2.f, rowp[v], sqj + g_sq[v]), 0.f);
    __syncthreads();

    const int ns = (nSame < POSCAP) ? nSame : POSCAP;
    if (tid < ns)
        avals[tid] = pdrow[(int)slist[tid]] + MARGIN_A;

    float pdk0 = 3.4e38f, pdk1 = 3.4e38f;    // sentinels: never counted
    if (tid < n       && labs[tid]       != labj) pdk0 = pdrow[tid];
    if (tid + TTH < n && labs[tid + TTH] != labj) pdk1 = pdrow[tid + TTH];
    __syncthreads();

    float s = 0.f;
    int   c = 0;
    for (int q = 0; q < ns; q++) {
        const float aq = avals[q];
        const float v0 = aq - pdk0;
        const float v1 = aq - pdk1;
        if (v0 > 0.f) { s += v0; c++; }
        if (v1 > 0.f) { s += v1; c++; }
    }

    #pragma unroll
    for (int o = 16; o > 0; o >>= 1) {
        s += __shfl_down_sync(0xffffffffu, s, o);
        c += __shfl_down_sync(0xffffffffu, c, o);
    }
    if (lane == 0) { red_s[wid] = s; red_c[wid] = c; }
    __syncthreads();
    if (tid == 0) {
        float st = 0.f; int ct = 0;
        #pragma unroll
        for (int w = 0; w < TNW; w++) { st += red_s[w]; ct += red_c[w]; }
        g_ps[j] = st;
        g_pc[j] = ct;
    }
    pdl_launch_dependents();
}

// ---------------------------------------------------------------------------
// Final: single block, fp64 reduce of n partials (waits on triplet via PDL).
// ---------------------------------------------------------------------------
__global__ void final_kernel(float* __restrict__ out, int n) {
    __shared__ double red_s[4];
    __shared__ double red_c[4];
    const int tid  = threadIdx.x;
    const int lane = tid & 31;
    const int wid  = tid >> 5;

    pdl_wait();

    double s = 0.0, c = 0.0;
    for (int t = tid; t < n; t += 128) { s += (double)g_ps[t]; c += (double)g_pc[t]; }
    #pragma unroll
    for (int o = 16; o > 0; o >>= 1) {
        s += __shfl_down_sync(0xffffffffu, s, o);
        c += __shfl_down_sync(0xffffffffu, c, o);
    }
    if (lane == 0) { red_s[wid] = s; red_c[wid] = c; }
    __syncthreads();
    if (tid == 0) {
        double st = 0.0, ct = 0.0;
        #pragma unroll
        for (int w = 0; w < 4; w++) { st += red_s[w]; ct += red_c[w]; }
        out[0] = (ct > 0.0) ? (float)(st / (ct < 1.0 ? 1.0 : ct)) : 0.0f;
    }
}

extern "C" void kernel_launch(void* const* d_in, const int* in_sizes, int n_in,
                              void* d_out, int out_size) {
    const float* anchor   = (const float*)d_in[0];
    const float* positive = (const float*)d_in[1];
    const float* negative = (const float*)d_in[2];
    const int*   ind      = (const int*)d_in[3];

    const int n = in_sizes[3];          // 3B
    const int B = n / 3;
    const int D = in_sizes[0] / B;      // 128

    const int tot4  = n * (D >> 2);
    const int pgrid = (tot4 + 255) / 256;
    prep_kernel<<<pgrid, 256>>>(anchor, positive, negative, n, B, D);

    cudaLaunchAttribute attr[1];
    attr[0].id = cudaLaunchAttributeProgrammaticStreamSerialization;
    attr[0].val.programmaticStreamSerializationAllowed = 1;

    cudaLaunchConfig_t cfg = {};
    cfg.attrs = attr;
    cfg.numAttrs = 1;
    cfg.stream = 0;

    cfg.gridDim  = dim3((unsigned)((n + GTC - 1) / GTC), (unsigned)((n + GTR - 1) / GTR), 1);
    cfg.blockDim = dim3(128, 1, 1);
    cudaLaunchKernelEx(&cfg, gram_kernel, n, D);

    cfg.gridDim  = dim3((unsigned)n, 1, 1);
    cfg.blockDim = dim3(TTH, 1, 1);
    cudaLaunchKernelEx(&cfg, triplet_kernel, ind, n);

    cfg.gridDim  = dim3(1, 1, 1);
    cfg.blockDim = dim3(128, 1, 1);
    cudaLaunchKernelEx(&cfg, final_kernel, (float*)d_out, n);
}